// round 14
// baseline (speedup 1.0000x reference)
#include <cuda_runtime.h>
#include <cstdint>
#include <math.h>

// RZ gate dense matrix, N=12 (confirmed model):
//   output = 16,777,216 float32 (67 MB) = real part of the 4096x4096
//   complex64 matrix; zeros except out[4097*k] = cos(theta/2), k=0..4095.
//   theta = float32 at d_in[0].
//
// R9/R12/R13: three different SM store mechanisms all converge at ~5.0 TB/s
// (L2 42%, L1 49%, nothing saturated) -> chip-wide L2 WRITE-path ceiling for
// SM-originated stores. This round probes the copy-engine path instead:
// cudaMemsetAsync (graph memset node, CE fill) for the 67 MB of zeros, then
// a tiny kernel writes the 4096 diagonal values (16 KB).

static constexpr long long DIM = 4096;
static constexpr long long DSTRIDE = DIM + 1;   // 4097
static constexpr int BLOCK = 256;

__global__ void rz_diag_kernel(const float* __restrict__ theta_p,
                               float* __restrict__ outf,
                               long long nfloats) {
    int k = blockIdx.x * BLOCK + threadIdx.x;
    if (k >= (int)DIM) return;

    float theta = theta_p ? theta_p[0] : 0.f;
    if (!isfinite(theta)) theta = 0.f;
    float cosv = cosf(0.5f * theta);

    long long fidx = (long long)k * DSTRIDE;
    if (fidx < nfloats)
        outf[fidx] = cosv;
}

extern "C" void kernel_launch(void* const* d_in, const int* in_sizes, int n_in,
                              void* d_out, int out_size) {
    const float* theta = (n_in >= 1) ? (const float*)d_in[0] : nullptr;
    long long nfloats = (long long)out_size;    // buffer = out_size*4 bytes

    // Bulk zeros via the copy-engine fill path (graph memset node).
    cudaMemsetAsync(d_out, 0, (size_t)nfloats * 4, 0);

    // Diagonal: 4096 scattered floats.
    rz_diag_kernel<<<(int)((DIM + BLOCK - 1) / BLOCK), BLOCK>>>(
        theta, (float*)d_out, nfloats);
}